// round 14
// baseline (speedup 1.0000x reference)
#include <cuda_runtime.h>
#include <cuda_bf16.h>
#include <cstdint>

#define RR   128
#define CC   256
#define EMB  768
#define NH   12
#define DKD  64
#define NT   (RR * CC)          // 32768 tokens

typedef __nv_bfloat16 bf16;

// ---------------- scratch (__device__ globals, allocation-free) -------------
__device__ bf16 g_Xh[(size_t)NT * EMB];
__device__ bf16 g_Xl[(size_t)NT * EMB];
__device__ bf16 g_Wh[4][(size_t)EMB * EMB];
__device__ bf16 g_Wl[4][(size_t)EMB * EMB];
__device__ bf16 g_Qh[(size_t)CC * NH * RR * DKD];   // [c][h][i][d]
__device__ bf16 g_Ql[(size_t)CC * NH * RR * DKD];
__device__ bf16 g_Kh[(size_t)CC * NH * RR * DKD];
__device__ bf16 g_Kl[(size_t)CC * NH * RR * DKD];
__device__ bf16 g_Vh[(size_t)CC * NH * RR * DKD];   // [c][h][i][d]
__device__ bf16 g_Vl[(size_t)CC * NH * RR * DKD];
__device__ bf16 g_Ch[(size_t)NT * EMB];             // ctx hi/lo [t][e]
__device__ bf16 g_Cl[(size_t)NT * EMB];

// ---------------------------- helpers --------------------------------------
__device__ __forceinline__ uint32_t smem_u32(const void* p) {
    uint32_t a;
    asm("{ .reg .u64 t; cvta.to.shared.u64 t, %1; cvt.u32.u64 %0, t; }"
        : "=r"(a) : "l"(p));
    return a;
}
__device__ __forceinline__ void ldsm4(uint32_t* r, uint32_t addr) {
    asm volatile("ldmatrix.sync.aligned.m8n8.x4.shared.b16 {%0,%1,%2,%3}, [%4];"
                 : "=r"(r[0]), "=r"(r[1]), "=r"(r[2]), "=r"(r[3]) : "r"(addr));
}
__device__ __forceinline__ void ldsm4t(uint32_t* r, uint32_t addr) {
    asm volatile("ldmatrix.sync.aligned.m8n8.x4.trans.shared.b16 {%0,%1,%2,%3}, [%4];"
                 : "=r"(r[0]), "=r"(r[1]), "=r"(r[2]), "=r"(r[3]) : "r"(addr));
}
__device__ __forceinline__ void mma_bf16(float* c, const uint32_t* a,
                                         const uint32_t* b) {
    asm volatile(
        "mma.sync.aligned.m16n8k16.row.col.f32.bf16.bf16.f32 "
        "{%0,%1,%2,%3}, {%4,%5,%6,%7}, {%8,%9}, {%0,%1,%2,%3};"
        : "+f"(c[0]), "+f"(c[1]), "+f"(c[2]), "+f"(c[3])
        : "r"(a[0]), "r"(a[1]), "r"(a[2]), "r"(a[3]), "r"(b[0]), "r"(b[1]));
}
#define CP_ASYNC(dst, src) \
    asm volatile("cp.async.cg.shared.global [%0], [%1], 16;" \
                 :: "r"(dst), "l"(src) : "memory")
#define CP_COMMIT() asm volatile("cp.async.commit_group;" ::: "memory")
#define CP_WAIT(n)  asm volatile("cp.async.wait_group %0;" :: "n"(n) : "memory")

__device__ __forceinline__ void split1(float v, bf16& h, bf16& l) {
    h = __float2bfloat16(v);
    l = __float2bfloat16(v - __bfloat162float(h));
}

// ---------------------------------------------------------------------------
// fp32 -> (hi, lo) bf16 splits
// ---------------------------------------------------------------------------
__global__ __launch_bounds__(256) void split_kernel(
    const float* __restrict__ src, bf16* __restrict__ hi,
    bf16* __restrict__ lo, int n4)
{
    int i = blockIdx.x * blockDim.x + threadIdx.x;
    if (i >= n4) return;
    float4 v = ((const float4*)src)[i];
    float a[4] = {v.x, v.y, v.z, v.w};
    bf16 h[4], l[4];
#pragma unroll
    for (int j = 0; j < 4; j++) split1(a[j], h[j], l[j]);
    ((__nv_bfloat162*)hi)[2 * i + 0] = __halves2bfloat162(h[0], h[1]);
    ((__nv_bfloat162*)hi)[2 * i + 1] = __halves2bfloat162(h[2], h[3]);
    ((__nv_bfloat162*)lo)[2 * i + 0] = __halves2bfloat162(l[0], l[1]);
    ((__nv_bfloat162*)lo)[2 * i + 1] = __halves2bfloat162(l[2], l[3]);
}

__global__ __launch_bounds__(256) void split_w4_kernel(
    const float* __restrict__ w0, const float* __restrict__ w1,
    const float* __restrict__ w2, const float* __restrict__ w3,
    bf16* __restrict__ hiBase, bf16* __restrict__ loBase, int n4)
{
    const int j = blockIdx.y;
    const float* src = (j == 0) ? w0 : (j == 1) ? w1 : (j == 2) ? w2 : w3;
    bf16* hi = hiBase + (size_t)j * EMB * EMB;
    bf16* lo = loBase + (size_t)j * EMB * EMB;
    int i = blockIdx.x * blockDim.x + threadIdx.x;
    if (i >= n4) return;
    float4 v = ((const float4*)src)[i];
    float a[4] = {v.x, v.y, v.z, v.w};
    bf16 h[4], l[4];
#pragma unroll
    for (int k = 0; k < 4; k++) split1(a[k], h[k], l[k]);
    ((__nv_bfloat162*)hi)[2 * i + 0] = __halves2bfloat162(h[0], h[1]);
    ((__nv_bfloat162*)hi)[2 * i + 1] = __halves2bfloat162(h[2], h[3]);
    ((__nv_bfloat162*)lo)[2 * i + 0] = __halves2bfloat162(l[0], l[1]);
    ((__nv_bfloat162*)lo)[2 * i + 1] = __halves2bfloat162(l[2], l[3]);
}

// ---------------------------------------------------------------------------
// GEMM mainloop v2: 256x128 CTA tile, 512 threads, BK=32, 3-stage cp.async
// pipeline. Inner fragment/MMA code identical to R11 (accumulator-major
// order — R12 regression evidence; do not reorder).
// ---------------------------------------------------------------------------
#define BK        32
#define SSTR      40
#define TILE_AB   (256 * SSTR * 2)          // 20480 B (A tiles, 256 rows)
#define TILE_BB   (128 * SSTR * 2)          // 10240 B (B tiles, 128 rows)
#define STAGE_B   (2 * TILE_AB + 2 * TILE_BB)   // 61440 B
#define GEMM_SMEM (3 * STAGE_B)             // 184320 B (>= epilogue 139264)
#define NSTEP     (EMB / BK)                // 24
#define ESTR      136                        // bf16 epilogue smem stride
#define ESTR4     132                        // fp32 epilogue smem stride

__device__ __forceinline__ void gemm_mainloop(
    const bf16* __restrict__ Ah, const bf16* __restrict__ Al,
    const bf16* __restrict__ Bh, const bf16* __restrict__ Bl,
    int m0, int n0, uint32_t u0, int tid, float (&acc)[2][8][4])
{
    const int lane   = tid & 31;
    const int wid    = tid >> 5;            // 0..15
    const int warp_m = (wid & 7) << 5;      // 0..224
    const int warp_n = (wid >> 3) << 6;     // 0 / 64

    const int a_r = lane & 15;
    const int a_k = (lane >> 4) << 3;
    const int b_n = (lane & 7) + ((lane >> 4) << 3);
    const int b_k = ((lane >> 3) & 1) << 3;

    const int f_row = tid >> 2;             // 0..127
    const int f_c16 = tid & 3;              // chunk within 64B of row data

#define FILL(stage, k0) do {                                                   \
        const uint32_t sb = u0 + (stage) * STAGE_B;                            \
        /* A tiles: 256 rows, 2 passes */                                      \
        _Pragma("unroll")                                                      \
        for (int sub = 0; sub < 2; sub++) {                                    \
            const int row = f_row + sub * 128;                                 \
            CP_ASYNC(sb + row * (SSTR * 2) + f_c16 * 16,                       \
                     Ah + (size_t)(m0 + row) * EMB + (k0) + f_c16 * 8);        \
            CP_ASYNC(sb + TILE_AB + row * (SSTR * 2) + f_c16 * 16,             \
                     Al + (size_t)(m0 + row) * EMB + (k0) + f_c16 * 8);        \
        }                                                                      \
        /* B tiles: 128 rows, 1 pass each */                                   \
        CP_ASYNC(sb + 2 * TILE_AB + f_row * (SSTR * 2) + f_c16 * 16,           \
                 Bh + (size_t)(n0 + f_row) * EMB + (k0) + f_c16 * 8);          \
        CP_ASYNC(sb + 2 * TILE_AB + TILE_BB + f_row * (SSTR * 2) + f_c16 * 16, \
                 Bl + (size_t)(n0 + f_row) * EMB + (k0) + f_c16 * 8);          \
        CP_COMMIT();                                                           \
    } while (0)

    FILL(0, 0);
    FILL(1, BK);

    for (int s = 0; s < NSTEP; s++) {
        if (s + 1 < NSTEP) { CP_WAIT(1); }   // fill(s) done, fill(s+1) may fly
        else               { CP_WAIT(0); }
        __syncthreads();                     // + compute(s-1) done (stage reuse)
        if (s + 2 < NSTEP) FILL((s + 2) % 3, (s + 2) * BK);

        const uint32_t sb  = u0 + (s % 3) * STAGE_B;
        const uint32_t uAh = sb;
        const uint32_t uAl = sb + TILE_AB;
        const uint32_t uBh = sb + 2 * TILE_AB;
        const uint32_t uBl = sb + 2 * TILE_AB + TILE_BB;

#pragma unroll
        for (int ks = 0; ks < 2; ks++) {
            const int kk = ks << 4;
            uint32_t aH[2][4], aL[2][4];
#pragma unroll
            for (int mi = 0; mi < 2; mi++) {
                const uint32_t off =
                    (uint32_t)((warp_m + mi * 16 + a_r) * SSTR + kk + a_k) * 2;
                ldsm4(aH[mi], uAh + off);
                ldsm4(aL[mi], uAl + off);
            }
#pragma unroll
            for (int np = 0; np < 4; np++) {
                uint32_t bH[4], bL[4];
                const uint32_t off =
                    (uint32_t)((warp_n + np * 16 + b_n) * SSTR + kk + b_k) * 2;
                ldsm4(bH, uBh + off);
                ldsm4(bL, uBl + off);
#pragma unroll
                for (int mi = 0; mi < 2; mi++) {
#pragma unroll
                    for (int ss = 0; ss < 2; ss++) {
                        float* c = acc[mi][np * 2 + ss];
                        mma_bf16(c, aH[mi], bH + 2 * ss);
                        mma_bf16(c, aL[mi], bH + 2 * ss);
                        mma_bf16(c, aH[mi], bL + 2 * ss);
                    }
                }
            }
        }
    }
    __syncthreads();   // mainloop smem free for epilogue staging
#undef FILL
}

// Fused QKV projection: blockIdx.z selects {Q, K, V}; outputs [c][h][i][d].
// m-tile = 256 tokens = one i-row x all 256 c.
__global__ __launch_bounds__(512, 1) void gemm_qkv(
    const bf16* __restrict__ Xh, const bf16* __restrict__ Xl,
    const bf16* __restrict__ WhB, const bf16* __restrict__ WlB,
    const float* __restrict__ bq, const float* __restrict__ bk,
    const float* __restrict__ bv,
    bf16* __restrict__ qh, bf16* __restrict__ ql,
    bf16* __restrict__ kh, bf16* __restrict__ kl,
    bf16* __restrict__ vh, bf16* __restrict__ vl)
{
    extern __shared__ char dsm[];
    const uint32_t u0 = smem_u32(dsm);
    const int tid  = threadIdx.x;
    const int lane = tid & 31;
    const int wid  = tid >> 5;
    const int m0 = blockIdx.y << 8;          // 256-aligned
    const int n0 = blockIdx.x << 7;
    const int z  = blockIdx.z;

    const size_t WSZ = (size_t)EMB * EMB;
    const bf16* Bh = WhB + (size_t)z * WSZ;
    const bf16* Bl = WlB + (size_t)z * WSZ;
    const float* bias = (z == 0) ? bq : (z == 1) ? bk : bv;
    const float scale = (z == 0) ? 0.125f : 1.0f;
    bf16* oh = (z == 0) ? qh : (z == 1) ? kh : vh;
    bf16* ol = (z == 0) ? ql : (z == 1) ? kl : vl;

    float acc[2][8][4];
#pragma unroll
    for (int mi = 0; mi < 2; mi++)
#pragma unroll
        for (int ni = 0; ni < 8; ni++)
#pragma unroll
            for (int q = 0; q < 4; q++) acc[mi][ni][q] = 0.f;

    gemm_mainloop(Xh, Xl, Bh, Bl, m0, n0, u0, tid, acc);

    // ---- stage to smem (bias + scale + split), then coalesced store ----
    bf16* Eh = (bf16*)dsm;                          // 256 x ESTR
    bf16* El = (bf16*)(dsm + 256 * ESTR * 2);
    const int warp_m = (wid & 7) << 5;
    const int warp_n = (wid >> 3) << 6;
#pragma unroll
    for (int mi = 0; mi < 2; mi++)
#pragma unroll
        for (int rr = 0; rr < 2; rr++) {
            const int row = warp_m + mi * 16 + rr * 8 + (lane >> 2);
#pragma unroll
            for (int ni = 0; ni < 8; ni++) {
                const int col = warp_n + ni * 8 + ((lane & 3) << 1);
                const float2 bv2 = *(const float2*)&bias[n0 + col];
                const float v0 = (acc[mi][ni][rr * 2 + 0] + bv2.x) * scale;
                const float v1 = (acc[mi][ni][rr * 2 + 1] + bv2.y) * scale;
                bf16 h0, l0, h1, l1;
                split1(v0, h0, l0); split1(v1, h1, l1);
                *(__nv_bfloat162*)&Eh[row * ESTR + col] = __halves2bfloat162(h0, h1);
                *(__nv_bfloat162*)&El[row * ESTR + col] = __halves2bfloat162(l0, l1);
            }
        }
    __syncthreads();

    const int irow = m0 >> 8;                // fixed i for this tile
    const int hh0  = n0 >> 6;
    // 256 rows (=c) x 16 chunks x 2 arrays = 8192 chunks / 512 threads
#pragma unroll
    for (int p = 0; p < 16; p++) {
        const int gid  = p * 512 + tid;
        const int arr  = gid >> 12;          // 0 hi, 1 lo
        const int r    = gid & 4095;
        const int crow = r >> 4;             // c value
        const int ch   = r & 15;
        const int hl   = ch >> 3;
        const int d8   = ch & 7;
        const bf16* src = arr ? El : Eh;
        uint4 v = *(const uint4*)&src[crow * ESTR + hl * 64 + d8 * 8];
        bf16* dst = arr ? ol : oh;
        *(uint4*)&dst[(((size_t)crow * NH + hh0 + hl) * RR + irow) * DKD + d8 * 8] = v;
    }
}

// Output projection: fp32 out, 256x128 tile, staged coalesced epilogue
__global__ __launch_bounds__(512, 1) void gemm_o(
    const bf16* __restrict__ Ch, const bf16* __restrict__ Cl,
    const bf16* __restrict__ Wh, const bf16* __restrict__ Wl,
    const float* __restrict__ bias, float* __restrict__ out)
{
    extern __shared__ char dsm[];
    const uint32_t u0 = smem_u32(dsm);
    const int tid  = threadIdx.x;
    const int lane = tid & 31;
    const int wid  = tid >> 5;
    const int m0 = blockIdx.y << 8;
    const int n0 = blockIdx.x << 7;

    float acc[2][8][4];
#pragma unroll
    for (int mi = 0; mi < 2; mi++)
#pragma unroll
        for (int ni = 0; ni < 8; ni++)
#pragma unroll
            for (int q = 0; q < 4; q++) acc[mi][ni][q] = 0.f;

    gemm_mainloop(Ch, Cl, Wh, Wl, m0, n0, u0, tid, acc);

    float* Ef = (float*)dsm;                 // 256 x ESTR4 fp32
    const int warp_m = (wid & 7) << 5;
    const int warp_n = (wid >> 3) << 6;
#pragma unroll
    for (int mi = 0; mi < 2; mi++)
#pragma unroll
        for (int rr = 0; rr < 2; rr++) {
            const int row = warp_m + mi * 16 + rr * 8 + (lane >> 2);
#pragma unroll
            for (int ni = 0; ni < 8; ni++) {
                const int col = warp_n + ni * 8 + ((lane & 3) << 1);
                const float2 bv2 = *(const float2*)&bias[n0 + col];
                *(float2*)&Ef[row * ESTR4 + col] =
                    make_float2(acc[mi][ni][rr * 2 + 0] + bv2.x,
                                acc[mi][ni][rr * 2 + 1] + bv2.y);
            }
        }
    __syncthreads();
    // 256 rows x 32 chunks (16B) = 8192 / 512 threads
#pragma unroll
    for (int p = 0; p < 16; p++) {
        const int gid = p * 512 + tid;
        const int row = gid >> 5;
        const int ch  = gid & 31;
        float4 v = *(const float4*)&Ef[row * ESTR4 + ch * 4];
        *(float4*)&out[(size_t)(m0 + row) * EMB + n0 + ch * 4] = v;
    }
}

// ---------------------------------------------------------------------------
// Tensor-core attention (byte-identical to R11 — proven 179us)
// ---------------------------------------------------------------------------
#define QS 72
#define PS 136

#define AOFF_QH  0
#define AOFF_QL  (AOFF_QH + 128 * QS * 2)
#define AOFF_KH  (AOFF_QL + 128 * QS * 2)
#define AOFF_KL  (AOFF_KH + 128 * QS * 2)
#define AOFF_VH  (AOFF_KL + 128 * QS * 2)
#define AOFF_VL  (AOFF_VH + 128 * QS * 2)
#define AOFF_ST  (AOFF_VL + 128 * QS * 2)
#define AOFF_MK  (AOFF_ST + 2048)
#define ATTN_SMEM (AOFF_MK + 128)
#define AOFF_PH  0
#define AOFF_PL  (AOFF_PH + 128 * PS * 2)
#define AOFF_CH  0
#define AOFF_CL  (AOFF_CH + 128 * QS * 2)

__global__ __launch_bounds__(256, 2) void attn_mma(
    const bf16* __restrict__ qh, const bf16* __restrict__ ql,
    const bf16* __restrict__ kh, const bf16* __restrict__ kl,
    const bf16* __restrict__ vh, const bf16* __restrict__ vl,
    const unsigned char* __restrict__ mask,
    float* __restrict__ probs, int write_probs)
{
    extern __shared__ char dsm[];
    const uint32_t u0 = smem_u32(dsm);
    float* sMax = (float*)(dsm + AOFF_ST);
    float* sSum = sMax + 256;
    unsigned char* sMask = (unsigned char*)(dsm + AOFF_MK);

    const int c   = blockIdx.x;
    const int h   = blockIdx.y;
    const int tid = threadIdx.x;
    const int lane = tid & 31;
    const int wid  = tid >> 5;
    const size_t base = (((size_t)c * NH + h) * RR) * DKD;

    {
        const int row_q = tid >> 1;
        const int c16_q = tid & 1;
        const bf16* srcs[6] = {qh, ql, kh, kl, vh, vl};
        const uint32_t dsts[6] = {u0 + AOFF_QH, u0 + AOFF_QL,
                                  u0 + AOFF_KH, u0 + AOFF_KL,
                                  u0 + AOFF_VH, u0 + AOFF_VL};
#pragma unroll
        for (int t = 0; t < 6; t++) {
#pragma unroll
            for (int sub = 0; sub < 4; sub++) {
                const int cid = sub * 2 + c16_q;
                CP_ASYNC(dsts[t] + row_q * (QS * 2) + cid * 16,
                         srcs[t] + base + (size_t)row_q * DKD + cid * 8);
            }
        }
        CP_COMMIT();
        if (tid < 128) sMask[tid] = mask[(size_t)tid * CC + c];
        CP_WAIT(0);
    }
    __syncthreads();

    const int a_r = lane & 15;
    const int a_k = (lane >> 4) << 3;
    const int b_n = (lane & 7) + ((lane >> 4) << 3);
    const int b_k = ((lane >> 3) & 1) << 3;
    const int v_r = (((lane >> 3) & 1) << 3) + (lane & 7);
    const int v_c = (lane >> 4) << 3;
    const int warp_m = (wid & 3) << 5;
    const int half   = wid >> 2;
    const int warp_n = half << 6;

    float acc[2][8][4];
#pragma unroll
    for (int mi = 0; mi < 2; mi++)
#pragma unroll
        for (int ni = 0; ni < 8; ni++)
#pragma unroll
            for (int q = 0; q < 4; q++) acc[mi][ni][q] = 0.f;

#pragma unroll
    for (int ks = 0; ks < 4; ks++) {
        const int kk = ks << 4;
        uint32_t aH[2][4], aL[2][4];
#pragma unroll
        for (int mi = 0; mi < 2; mi++) {
            const uint32_t off =
                (uint32_t)((warp_m + mi * 16 + a_r) * QS + kk + a_k) * 2;
            ldsm4(aH[mi], u0 + AOFF_QH + off);
            ldsm4(aL[mi], u0 + AOFF_QL + off);
        }
#pragma unroll
        for (int np = 0; np < 4; np++) {
            uint32_t bH[4], bL[4];
            const uint32_t off =
                (uint32_t)((warp_n + np * 16 + b_n) * QS + kk + b_k) * 2;
            ldsm4(bH, u0 + AOFF_KH + off);
            ldsm4(bL, u0 + AOFF_KL + off);
#pragma unroll
            for (int mi = 0; mi < 2; mi++) {
#pragma unroll
                for (int ss = 0; ss < 2; ss++) {
                    float* cp = acc[mi][np * 2 + ss];
                    mma_bf16(cp, aH[mi], bH + 2 * ss);
                    mma_bf16(cp, aL[mi], bH + 2 * ss);
                    mma_bf16(cp, aH[mi], bL + 2 * ss);
                }
            }
        }
    }

#pragma unroll
    for (int ni = 0; ni < 8; ni++) {
        const int c0 = warp_n + ni * 8 + ((lane & 3) << 1);
        if (sMask[c0]) {
            acc[0][ni][0] = -10000.f; acc[0][ni][2] = -10000.f;
            acc[1][ni][0] = -10000.f; acc[1][ni][2] = -10000.f;
        }
        if (sMask[c0 + 1]) {
            acc[0][ni][1] = -10000.f; acc[0][ni][3] = -10000.f;
            acc[1][ni][1] = -10000.f; acc[1][ni][3] = -10000.f;
        }
    }

#pragma unroll
    for (int mi = 0; mi < 2; mi++)
#pragma unroll
        for (int rr = 0; rr < 2; rr++) {
            float mx = -1e30f;
#pragma unroll
            for (int ni = 0; ni < 8; ni++) {
                mx = fmaxf(mx, acc[mi][ni][rr * 2 + 0]);
                mx = fmaxf(mx, acc[mi][ni][rr * 2 + 1]);
            }
            mx = fmaxf(mx, __shfl_xor_sync(0xFFFFFFFFu, mx, 1));
            mx = fmaxf(mx, __shfl_xor_sync(0xFFFFFFFFu, mx, 2));
            const int row = warp_m + mi * 16 + rr * 8 + (lane >> 2);
            if ((lane & 3) == 0) sMax[half * 128 + row] = mx;
        }
    __syncthreads();

#pragma unroll
    for (int mi = 0; mi < 2; mi++)
#pragma unroll
        for (int rr = 0; rr < 2; rr++) {
            const int row = warp_m + mi * 16 + rr * 8 + (lane >> 2);
            const float m = fmaxf(sMax[row], sMax[128 + row]);
            float s = 0.f;
#pragma unroll
            for (int ni = 0; ni < 8; ni++) {
                float e0 = __expf(acc[mi][ni][rr * 2 + 0] - m);
                float e1 = __expf(acc[mi][ni][rr * 2 + 1] - m);
                acc[mi][ni][rr * 2 + 0] = e0;
                acc[mi][ni][rr * 2 + 1] = e1;
                s += e0 + e1;
            }
            s += __shfl_xor_sync(0xFFFFFFFFu, s, 1);
            s += __shfl_xor_sync(0xFFFFFFFFu, s, 2);
            if ((lane & 3) == 0) sSum[half * 128 + row] = s;
        }
    __syncthreads();

    {
        bf16* Ph = (bf16*)(dsm + AOFF_PH);
        bf16* Pl = (bf16*)(dsm + AOFF_PL);
#pragma unroll
        for (int mi = 0; mi < 2; mi++)
#pragma unroll
            for (int rr = 0; rr < 2; rr++) {
                const int row = warp_m + mi * 16 + rr * 8 + (lane >> 2);
                const float inv = 1.f / (sSum[row] + sSum[128 + row]);
#pragma unroll
                for (int ni = 0; ni < 8; ni++) {
                    const int col = warp_n + ni * 8 + ((lane & 3) << 1);
                    const float p0 = acc[mi][ni][rr * 2 + 0] * inv;
                    const float p1 = acc[mi][ni][rr * 2 + 1] * inv;
                    bf16 h0, l0, h1, l1;
                    split1(p0, h0, l0); split1(p1, h1, l1);
                    *(__nv_bfloat162*)&Ph[row * PS + col] = __halves2bfloat162(h0, h1);
                    *(__nv_bfloat162*)&Pl[row * PS + col] = __halves2bfloat162(l0, l1);
                }
            }
    }
    __syncthreads();

    if (write_probs) {
        const bf16* Ph = (const bf16*)(dsm + AOFF_PH);
        const bf16* Pl = (const bf16*)(dsm + AOFF_PL);
        float* pb = probs + (((size_t)h * CC + c) * RR) * RR;
#pragma unroll
        for (int p = 0; p < 16; p++) {
            const int row = p * 8 + (tid >> 5);
            const int col = (lane) * 4;
            const __nv_bfloat162* hp = (const __nv_bfloat162*)&Ph[row * PS + col];
            const __nv_bfloat162* lp = (const __nv_bfloat162*)&Pl[row * PS + col];
            float2 h0 = __bfloat1622float2(hp[0]);
            float2 h1 = __bfloat1622float2(hp[1]);
            float2 l0 = __bfloat1622float2(lp[0]);
            float2 l1 = __bfloat1622float2(lp[1]);
            float4 v = make_float4(h0.x + l0.x, h0.y + l0.y,
                                   h1.x + l1.x, h1.y + l1.y);
            *(float4*)&pb[(size_t)row * RR + col] = v;
        }
    }

    float acc2[2][4][4];
#pragma unroll
    for (int mi = 0; mi < 2; mi++)
#pragma unroll
        for (int ni = 0; ni < 4; ni++)
#pragma unroll
            for (int q = 0; q < 4; q++) acc2[mi][ni][q] = 0.f;

    {
        const int warp_nd = half << 5;
#pragma unroll
        for (int ks = 0; ks < 8; ks++) {
            const int kk = ks << 4;
            uint32_t aH[2][4], aL[2][4];
#pragma unroll
            for (int mi = 0; mi < 2; mi++) {
                const uint32_t off =
                    (uint32_t)((warp_m + mi * 16 + a_r) * PS + kk + a_k) * 2;
                ldsm4(aH[mi], u0 + AOFF_PH + off);
                ldsm4(aL[mi], u0 + AOFF_PL + off);
            }
#pragma unroll
            for (int np = 0; np < 2; np++) {
                uint32_t bH[4], bL[4];
                const uint32_t off =
                    (uint32_t)((kk + v_r) * QS + warp_nd + np * 16 + v_c) * 2;
                ldsm4t(bH, u0 + AOFF_VH + off);
                ldsm4t(bL, u0 + AOFF_VL + off);
#pragma unroll
                for (int mi = 0; mi < 2; mi++) {
#pragma unroll
                    for (int ss = 0; ss < 2; ss++) {
                        float* cp = acc2[mi][np * 2 + ss];
                        mma_bf16(cp, aH[mi], bH + 2 * ss);
                        mma_bf16(cp, aH[mi], bL + 2 * ss);
                        mma_bf16(cp, aL[mi], bH + 2 * ss);
                    }
                }
            }
        }
    }
    __syncthreads();

    {
        bf16* Chs = (bf16*)(dsm + AOFF_CH);
        bf16* Cls = (bf16*)(dsm + AOFF_CL);
        const int warp_nd = half << 5;
#pragma unroll
        for (int mi = 0; mi < 2; mi++)
#pragma unroll
            for (int rr = 0; rr < 2; rr++) {
                const int i = warp_m + mi * 16 + rr * 8 + (lane >> 2);
#pragma unroll
                for (int ni = 0; ni < 4; ni++) {
                    const int d = warp_nd + ni * 8 + ((lane & 3) << 1);
                    bf16 h0, l0, h1, l1;
                    split1(acc2[mi][ni][rr * 2 + 0], h0, l0);
                    split1(acc2[mi][ni][rr * 2 + 1], h1, l1);
                    *(__nv_bfloat162*)&Chs[i * QS + d] = __halves2bfloat162(h0, h1);
                    *(__nv_bfloat162*)&Cls[i * QS + d] = __halves2bfloat162(l0, l1);
                }
            }
    }
    __syncthreads();
    {
        const bf16* Chs = (const bf16*)(dsm + AOFF_CH);
        const bf16* Cls = (const bf16*)(dsm + AOFF_CL);
#pragma unroll
        for (int p = 0; p < 8; p++) {
            const int lr = p * 32 + (tid >> 3);
            const int arr = lr >> 7;
            const int i = lr & 127;
            const bf16* src = arr ? Cls : Chs;
            uint4 v = *(const uint4*)&src[i * QS + (tid & 7) * 8];
            bf16* dst = arr ? g_Cl : g_Ch;
            *(uint4*)&dst[((size_t)i * CC + c) * EMB + h * DKD + (tid & 7) * 8] = v;
        }
    }
}

// ---------------------------------------------------------------------------
extern "C" void kernel_launch(void* const* d_in, const int* in_sizes, int n_in,
                              void* d_out, int out_size)
{
    const float*         x    = (const float*)d_in[0];
    const unsigned char* mask = (const unsigned char*)d_in[1];
    const float* Wq = (const float*)d_in[2];
    const float* bq = (const float*)d_in[3];
    const float* Wk = (const float*)d_in[4];
    const float* bk = (const float*)d_in[5];
    const float* Wv = (const float*)d_in[6];
    const float* bv = (const float*)d_in[7];
    const float* Wo = (const float*)d_in[8];
    const float* bo = (const float*)d_in[9];
    float* out = (float*)d_out;

    const long long OUT_E   = (long long)NT * EMB;
    const long long PROBS_E = (long long)NH * CC * RR * RR;

    float* probs = nullptr;
    int write_probs = 0;
    int do_output = 1;
    if ((long long)out_size >= OUT_E + PROBS_E) {
        probs = out + OUT_E;
        write_probs = 1;
    } else if ((long long)out_size == PROBS_E) {
        probs = out;
        write_probs = 1;
        do_output = 0;
    }

    void *xh, *xl, *wh, *wl, *qh_, *ql_, *kh_, *kl_, *vh_, *vl_, *ch, *cl;
    cudaGetSymbolAddress(&xh, g_Xh);  cudaGetSymbolAddress(&xl, g_Xl);
    cudaGetSymbolAddress(&wh, g_Wh);  cudaGetSymbolAddress(&wl, g_Wl);
    cudaGetSymbolAddress(&qh_, g_Qh); cudaGetSymbolAddress(&ql_, g_Ql);
    cudaGetSymbolAddress(&kh_, g_Kh); cudaGetSymbolAddress(&kl_, g_Kl);
    cudaGetSymbolAddress(&vh_, g_Vh); cudaGetSymbolAddress(&vl_, g_Vl);
    cudaGetSymbolAddress(&ch, g_Ch);  cudaGetSymbolAddress(&cl, g_Cl);

    bf16* Xh = (bf16*)xh; bf16* Xl = (bf16*)xl;
    bf16* Wh = (bf16*)wh; bf16* Wl = (bf16*)wl;
    const size_t WSZ = (size_t)EMB * EMB;

    static int attr_set = 0;
    if (!attr_set) {
        cudaFuncSetAttribute(gemm_qkv,
                             cudaFuncAttributeMaxDynamicSharedMemorySize, GEMM_SMEM);
        cudaFuncSetAttribute(gemm_o,
                             cudaFuncAttributeMaxDynamicSharedMemorySize, GEMM_SMEM);
        cudaFuncSetAttribute(attn_mma,
                             cudaFuncAttributeMaxDynamicSharedMemorySize, ATTN_SMEM);
        attr_set = 1;
    }

    split_kernel<<<(NT * EMB / 4 + 255) / 256, 256>>>(x, Xh, Xl, NT * EMB / 4);
    split_w4_kernel<<<dim3((unsigned)((WSZ / 4 + 255) / 256), 4), 256>>>(
        Wq, Wk, Wv, Wo, Wh, Wl, (int)(WSZ / 4));

    gemm_qkv<<<dim3(6, 128, 3), 512, GEMM_SMEM>>>(
        Xh, Xl, Wh, Wl, bq, bk, bv,
        (bf16*)qh_, (bf16*)ql_, (bf16*)kh_, (bf16*)kl_, (bf16*)vh_, (bf16*)vl_);

    attn_mma<<<dim3(CC, NH), 256, ATTN_SMEM>>>(
        (const bf16*)qh_, (const bf16*)ql_, (const bf16*)kh_, (const bf16*)kl_,
        (const bf16*)vh_, (const bf16*)vl_, mask, probs, write_probs);

    if (do_output)
        gemm_o<<<dim3(6, 128), 512, GEMM_SMEM>>>(
            (const bf16*)ch, (const bf16*)cl, Wh + 3 * WSZ, Wl + 3 * WSZ, bo, out);
}

// round 15
// speedup vs baseline: 1.4219x; 1.4219x over previous
#include <cuda_runtime.h>
#include <cuda_fp16.h>
#include <cstdint>

#define RR   128
#define CC   256
#define EMB  768
#define NH   12
#define DKD  64
#define NT   (RR * CC)          // 32768 tokens

typedef __half hf;

// ---------------- scratch (__device__ globals, allocation-free) -------------
__device__ hf g_Xh[(size_t)NT * EMB];
__device__ hf g_Xl[(size_t)NT * EMB];
__device__ hf g_Wh[4][(size_t)EMB * EMB];           // W hi only (2-term GEMM)
__device__ hf g_Qh[(size_t)CC * NH * RR * DKD];     // [c][h][i][d]
__device__ hf g_Ql[(size_t)CC * NH * RR * DKD];
__device__ hf g_Kh[(size_t)CC * NH * RR * DKD];
__device__ hf g_Kl[(size_t)CC * NH * RR * DKD];
__device__ hf g_Vh[(size_t)CC * NH * RR * DKD];     // [c][h][i][d]
__device__ hf g_Vl[(size_t)CC * NH * RR * DKD];
__device__ hf g_Ch[(size_t)NT * EMB];               // ctx hi/lo [t][e]
__device__ hf g_Cl[(size_t)NT * EMB];

// ---------------------------- helpers --------------------------------------
__device__ __forceinline__ uint32_t smem_u32(const void* p) {
    uint32_t a;
    asm("{ .reg .u64 t; cvta.to.shared.u64 t, %1; cvt.u32.u64 %0, t; }"
        : "=r"(a) : "l"(p));
    return a;
}
__device__ __forceinline__ void ldsm4(uint32_t* r, uint32_t addr) {
    asm volatile("ldmatrix.sync.aligned.m8n8.x4.shared.b16 {%0,%1,%2,%3}, [%4];"
                 : "=r"(r[0]), "=r"(r[1]), "=r"(r[2]), "=r"(r[3]) : "r"(addr));
}
__device__ __forceinline__ void ldsm4t(uint32_t* r, uint32_t addr) {
    asm volatile("ldmatrix.sync.aligned.m8n8.x4.trans.shared.b16 {%0,%1,%2,%3}, [%4];"
                 : "=r"(r[0]), "=r"(r[1]), "=r"(r[2]), "=r"(r[3]) : "r"(addr));
}
__device__ __forceinline__ void mma_f16(float* c, const uint32_t* a,
                                        const uint32_t* b) {
    asm volatile(
        "mma.sync.aligned.m16n8k16.row.col.f32.f16.f16.f32 "
        "{%0,%1,%2,%3}, {%4,%5,%6,%7}, {%8,%9}, {%0,%1,%2,%3};"
        : "+f"(c[0]), "+f"(c[1]), "+f"(c[2]), "+f"(c[3])
        : "r"(a[0]), "r"(a[1]), "r"(a[2]), "r"(a[3]), "r"(b[0]), "r"(b[1]));
}
#define CP_ASYNC(dst, src) \
    asm volatile("cp.async.cg.shared.global [%0], [%1], 16;" \
                 :: "r"(dst), "l"(src) : "memory")
#define CP_COMMIT() asm volatile("cp.async.commit_group;" ::: "memory")
#define CP_WAIT(n)  asm volatile("cp.async.wait_group %0;" :: "n"(n) : "memory")

__device__ __forceinline__ void split1(float v, hf& h, hf& l) {
    h = __float2half_rn(v);
    l = __float2half_rn(v - __half2float(h));
}

// ---------------------------------------------------------------------------
// fp32 -> (hi, lo) fp16 splits
// ---------------------------------------------------------------------------
__global__ __launch_bounds__(256) void split_kernel(
    const float* __restrict__ src, hf* __restrict__ hi,
    hf* __restrict__ lo, int n4)
{
    int i = blockIdx.x * blockDim.x + threadIdx.x;
    if (i >= n4) return;
    float4 v = ((const float4*)src)[i];
    float a[4] = {v.x, v.y, v.z, v.w};
    hf h[4], l[4];
#pragma unroll
    for (int j = 0; j < 4; j++) split1(a[j], h[j], l[j]);
    ((__half2*)hi)[2 * i + 0] = __halves2half2(h[0], h[1]);
    ((__half2*)hi)[2 * i + 1] = __halves2half2(h[2], h[3]);
    ((__half2*)lo)[2 * i + 0] = __halves2half2(l[0], l[1]);
    ((__half2*)lo)[2 * i + 1] = __halves2half2(l[2], l[3]);
}

// all 4 weight matrices, hi only (W-lo term dropped in 2-term GEMM)
__global__ __launch_bounds__(256) void split_w4_kernel(
    const float* __restrict__ w0, const float* __restrict__ w1,
    const float* __restrict__ w2, const float* __restrict__ w3,
    hf* __restrict__ hiBase, int n4)
{
    const int j = blockIdx.y;
    const float* src = (j == 0) ? w0 : (j == 1) ? w1 : (j == 2) ? w2 : w3;
    hf* hi = hiBase + (size_t)j * EMB * EMB;
    int i = blockIdx.x * blockDim.x + threadIdx.x;
    if (i >= n4) return;
    float4 v = ((const float4*)src)[i];
    ((__half2*)hi)[2 * i + 0] =
        __halves2half2(__float2half_rn(v.x), __float2half_rn(v.y));
    ((__half2*)hi)[2 * i + 1] =
        __halves2half2(__float2half_rn(v.z), __float2half_rn(v.w));
}

// ---------------------------------------------------------------------------
// GEMM mainloop: 128x128 CTA tile, BK=32, 2-stage cp.async pipeline,
// 2-term fp16 mma: D = Ah*Bh + Al*Bh (W-lo dropped; fp16 keeps err ~2^-12).
// Accumulator-major MMA order (R12 regression evidence — do not reorder).
// ---------------------------------------------------------------------------
#define BK        32
#define SSTR      40
#define TILE_B    (128 * SSTR * 2)          // 10240 B
#define STAGE_B   (3 * TILE_B)              // 30720 B (Ah, Al, Bh)
#define ESTR      136                        // f16 epilogue smem stride
#define ESTR4     132                        // fp32 epilogue smem stride
#define GEMM_SMEM (128 * ESTR * 2 * 2)      // 69632 B (>= 2*STAGE_B=61440)
#define NSTEP     (EMB / BK)                // 24

__device__ __forceinline__ void gemm_mainloop(
    const hf* __restrict__ Ah, const hf* __restrict__ Al,
    const hf* __restrict__ Bh,
    int m0, int n0, uint32_t u0, int tid, float (&acc)[2][8][4])
{
    const int lane   = tid & 31;
    const int wid    = tid >> 5;
    const int warp_m = (wid & 3) << 5;
    const int warp_n = (wid >> 2) << 6;

    const int a_r = lane & 15;
    const int a_k = (lane >> 4) << 3;
    const int b_n = (lane & 7) + ((lane >> 4) << 3);
    const int b_k = ((lane >> 3) & 1) << 3;

    const int f_row = tid >> 2;
    const int f_c16 = tid & 3;

#define FILL(stage, k0) do {                                                   \
        const uint32_t sb = u0 + (stage) * STAGE_B;                            \
        _Pragma("unroll")                                                      \
        for (int t = 0; t < 3; t++) {                                          \
            const hf* sp = (t == 0) ? Ah : (t == 1) ? Al : Bh;                 \
            const int rb = (t < 2) ? m0 : n0;                                  \
            _Pragma("unroll")                                                  \
            for (int sub = 0; sub < 2; sub++) {                                \
                const int row = f_row + sub * 64;                              \
                CP_ASYNC(sb + t * TILE_B + row * (SSTR * 2) + f_c16 * 16,      \
                         sp + (size_t)(rb + row) * EMB + (k0) + f_c16 * 8);    \
            }                                                                  \
        }                                                                      \
        CP_COMMIT();                                                           \
    } while (0)

    FILL(0, 0);

    for (int s = 0; s < NSTEP; s++) {
        CP_WAIT(0);
        __syncthreads();               // copies visible + prev compute done
        if (s + 1 < NSTEP) FILL((s + 1) & 1, (s + 1) * BK);

        const uint32_t sb  = u0 + (s & 1) * STAGE_B;
        const uint32_t uAh = sb;
        const uint32_t uAl = sb + TILE_B;
        const uint32_t uBh = sb + 2 * TILE_B;

#pragma unroll
        for (int ks = 0; ks < 2; ks++) {
            const int kk = ks << 4;
            uint32_t aH[2][4], aL[2][4];
#pragma unroll
            for (int mi = 0; mi < 2; mi++) {
                const uint32_t off =
                    (uint32_t)((warp_m + mi * 16 + a_r) * SSTR + kk + a_k) * 2;
                ldsm4(aH[mi], uAh + off);
                ldsm4(aL[mi], uAl + off);
            }
#pragma unroll
            for (int np = 0; np < 4; np++) {
                uint32_t bH[4];
                const uint32_t off =
                    (uint32_t)((warp_n + np * 16 + b_n) * SSTR + kk + b_k) * 2;
                ldsm4(bH, uBh + off);
#pragma unroll
                for (int mi = 0; mi < 2; mi++) {
#pragma unroll
                    for (int ss = 0; ss < 2; ss++) {
                        float* c = acc[mi][np * 2 + ss];
                        mma_f16(c, aH[mi], bH + 2 * ss);
                        mma_f16(c, aL[mi], bH + 2 * ss);
                    }
                }
            }
        }
        __syncthreads();   // compute done before next FILL overwrites stage
    }
#undef FILL
}

// Fused QKV projection: blockIdx.z selects {Q, K, V}; outputs [c][h][i][d]
__global__ __launch_bounds__(256, 2) void gemm_qkv(
    const hf* __restrict__ Xh, const hf* __restrict__ Xl,
    const hf* __restrict__ WhB,
    const float* __restrict__ bq, const float* __restrict__ bk,
    const float* __restrict__ bv,
    hf* __restrict__ qh, hf* __restrict__ ql,
    hf* __restrict__ kh, hf* __restrict__ kl,
    hf* __restrict__ vh, hf* __restrict__ vl)
{
    extern __shared__ char dsm[];
    const uint32_t u0 = smem_u32(dsm);
    const int tid  = threadIdx.x;
    const int lane = tid & 31;
    const int wid  = tid >> 5;
    const int m0 = blockIdx.y << 7;
    const int n0 = blockIdx.x << 7;
    const int z  = blockIdx.z;

    const size_t WSZ = (size_t)EMB * EMB;
    const hf* Bh = WhB + (size_t)z * WSZ;
    const float* bias = (z == 0) ? bq : (z == 1) ? bk : bv;
    const float scale = (z == 0) ? 0.125f : 1.0f;
    hf* oh = (z == 0) ? qh : (z == 1) ? kh : vh;
    hf* ol = (z == 0) ? ql : (z == 1) ? kl : vl;

    float acc[2][8][4];
#pragma unroll
    for (int mi = 0; mi < 2; mi++)
#pragma unroll
        for (int ni = 0; ni < 8; ni++)
#pragma unroll
            for (int q = 0; q < 4; q++) acc[mi][ni][q] = 0.f;

    gemm_mainloop(Xh, Xl, Bh, m0, n0, u0, tid, acc);
    __syncthreads();   // mainloop smem free for epilogue staging

    // ---- stage to smem (bias + scale + split), then coalesced store ----
    hf* Eh = (hf*)dsm;
    hf* El = (hf*)(dsm + 128 * ESTR * 2);
    const int warp_m = (wid & 3) << 5;
    const int warp_n = (wid >> 2) << 6;
#pragma unroll
    for (int mi = 0; mi < 2; mi++)
#pragma unroll
        for (int rr = 0; rr < 2; rr++) {
            const int row = warp_m + mi * 16 + rr * 8 + (lane >> 2);
#pragma unroll
            for (int ni = 0; ni < 8; ni++) {
                const int col = warp_n + ni * 8 + ((lane & 3) << 1);
                const float2 bv2 = *(const float2*)&bias[n0 + col];
                const float v0 = (acc[mi][ni][rr * 2 + 0] + bv2.x) * scale;
                const float v1 = (acc[mi][ni][rr * 2 + 1] + bv2.y) * scale;
                hf h0, l0, h1, l1;
                split1(v0, h0, l0); split1(v1, h1, l1);
                *(__half2*)&Eh[row * ESTR + col] = __halves2half2(h0, h1);
                *(__half2*)&El[row * ESTR + col] = __halves2half2(l0, l1);
            }
        }
    __syncthreads();

    const int irow  = m0 >> 8;
    const int ccol0 = m0 & 255;
    const int hh0   = n0 >> 6;
#pragma unroll
    for (int p = 0; p < 16; p++) {
        const int lr = p * 32 + (tid >> 3);   // 0..511
        const int arr = lr >> 8;              // 0 hi, 1 lo
        const int r = lr & 255;
        const int ml = r >> 1;
        const int hl = r & 1;
        const hf* src = arr ? El : Eh;
        uint4 v = *(const uint4*)&src[ml * ESTR + hl * 64 + (tid & 7) * 8];
        hf* dst = arr ? ol : oh;
        *(uint4*)&dst[(((size_t)(ccol0 + ml) * NH + hh0 + hl) * RR + irow) * DKD
                      + (tid & 7) * 8] = v;
    }
}

// Output projection: fp32 out, staged epilogue
__global__ __launch_bounds__(256, 2) void gemm_o(
    const hf* __restrict__ Ch, const hf* __restrict__ Cl,
    const hf* __restrict__ Wh,
    const float* __restrict__ bias, float* __restrict__ out)
{
    extern __shared__ char dsm[];
    const uint32_t u0 = smem_u32(dsm);
    const int tid  = threadIdx.x;
    const int lane = tid & 31;
    const int wid  = tid >> 5;
    const int m0 = blockIdx.y << 7;
    const int n0 = blockIdx.x << 7;

    float acc[2][8][4];
#pragma unroll
    for (int mi = 0; mi < 2; mi++)
#pragma unroll
        for (int ni = 0; ni < 8; ni++)
#pragma unroll
            for (int q = 0; q < 4; q++) acc[mi][ni][q] = 0.f;

    gemm_mainloop(Ch, Cl, Wh, m0, n0, u0, tid, acc);
    __syncthreads();

    float* Ef = (float*)dsm;
    const int warp_m = (wid & 3) << 5;
    const int warp_n = (wid >> 2) << 6;
#pragma unroll
    for (int mi = 0; mi < 2; mi++)
#pragma unroll
        for (int rr = 0; rr < 2; rr++) {
            const int row = warp_m + mi * 16 + rr * 8 + (lane >> 2);
#pragma unroll
            for (int ni = 0; ni < 8; ni++) {
                const int col = warp_n + ni * 8 + ((lane & 3) << 1);
                const float2 bv2 = *(const float2*)&bias[n0 + col];
                *(float2*)&Ef[row * ESTR4 + col] =
                    make_float2(acc[mi][ni][rr * 2 + 0] + bv2.x,
                                acc[mi][ni][rr * 2 + 1] + bv2.y);
            }
        }
    __syncthreads();
#pragma unroll
    for (int p = 0; p < 16; p++) {
        const int ml = p * 8 + (tid >> 5);
        float4 v = *(const float4*)&Ef[ml * ESTR4 + (tid & 31) * 4];
        *(float4*)&out[(size_t)(m0 + ml) * EMB + n0 + (tid & 31) * 4] = v;
    }
}

// ---------------------------------------------------------------------------
// Tensor-core attention (R11 structure, fp16; 3-term kept — DRAM-bound here)
// ---------------------------------------------------------------------------
#define QS 72
#define PS 136

#define AOFF_QH  0
#define AOFF_QL  (AOFF_QH + 128 * QS * 2)
#define AOFF_KH  (AOFF_QL + 128 * QS * 2)
#define AOFF_KL  (AOFF_KH + 128 * QS * 2)
#define AOFF_VH  (AOFF_KL + 128 * QS * 2)
#define AOFF_VL  (AOFF_VH + 128 * QS * 2)
#define AOFF_ST  (AOFF_VL + 128 * QS * 2)
#define AOFF_MK  (AOFF_ST + 2048)
#define ATTN_SMEM (AOFF_MK + 128)
#define AOFF_PH  0
#define AOFF_PL  (AOFF_PH + 128 * PS * 2)
#define AOFF_CH  0
#define AOFF_CL  (AOFF_CH + 128 * QS * 2)

__global__ __launch_bounds__(256, 2) void attn_mma(
    const hf* __restrict__ qh, const hf* __restrict__ ql,
    const hf* __restrict__ kh, const hf* __restrict__ kl,
    const hf* __restrict__ vh, const hf* __restrict__ vl,
    const unsigned char* __restrict__ mask,
    float* __restrict__ probs, int write_probs)
{
    extern __shared__ char dsm[];
    const uint32_t u0 = smem_u32(dsm);
    float* sMax = (float*)(dsm + AOFF_ST);
    float* sSum = sMax + 256;
    unsigned char* sMask = (unsigned char*)(dsm + AOFF_MK);

    const int c   = blockIdx.x;
    const int h   = blockIdx.y;
    const int tid = threadIdx.x;
    const int lane = tid & 31;
    const int wid  = tid >> 5;
    const size_t base = (((size_t)c * NH + h) * RR) * DKD;

    {
        const int row_q = tid >> 1;
        const int c16_q = tid & 1;
        const hf* srcs[6] = {qh, ql, kh, kl, vh, vl};
        const uint32_t dsts[6] = {u0 + AOFF_QH, u0 + AOFF_QL,
                                  u0 + AOFF_KH, u0 + AOFF_KL,
                                  u0 + AOFF_VH, u0 + AOFF_VL};
#pragma unroll
        for (int t = 0; t < 6; t++) {
#pragma unroll
            for (int sub = 0; sub < 4; sub++) {
                const int cid = sub * 2 + c16_q;
                CP_ASYNC(dsts[t] + row_q * (QS * 2) + cid * 16,
                         srcs[t] + base + (size_t)row_q * DKD + cid * 8);
            }
        }
        CP_COMMIT();
        if (tid < 128) sMask[tid] = mask[(size_t)tid * CC + c];
        CP_WAIT(0);
    }
    __syncthreads();

    const int a_r = lane & 15;
    const int a_k = (lane >> 4) << 3;
    const int b_n = (lane & 7) + ((lane >> 4) << 3);
    const int b_k = ((lane >> 3) & 1) << 3;
    const int v_r = (((lane >> 3) & 1) << 3) + (lane & 7);
    const int v_c = (lane >> 4) << 3;
    const int warp_m = (wid & 3) << 5;
    const int half   = wid >> 2;
    const int warp_n = half << 6;

    float acc[2][8][4];
#pragma unroll
    for (int mi = 0; mi < 2; mi++)
#pragma unroll
        for (int ni = 0; ni < 8; ni++)
#pragma unroll
            for (int q = 0; q < 4; q++) acc[mi][ni][q] = 0.f;

#pragma unroll
    for (int ks = 0; ks < 4; ks++) {
        const int kk = ks << 4;
        uint32_t aH[2][4], aL[2][4];
#pragma unroll
        for (int mi = 0; mi < 2; mi++) {
            const uint32_t off =
                (uint32_t)((warp_m + mi * 16 + a_r) * QS + kk + a_k) * 2;
            ldsm4(aH[mi], u0 + AOFF_QH + off);
            ldsm4(aL[mi], u0 + AOFF_QL + off);
        }
#pragma unroll
        for (int np = 0; np < 4; np++) {
            uint32_t bH[4], bL[4];
            const uint32_t off =
                (uint32_t)((warp_n + np * 16 + b_n) * QS + kk + b_k) * 2;
            ldsm4(bH, u0 + AOFF_KH + off);
            ldsm4(bL, u0 + AOFF_KL + off);
#pragma unroll
            for (int mi = 0; mi < 2; mi++) {
#pragma unroll
                for (int ss = 0; ss < 2; ss++) {
                    float* cp = acc[mi][np * 2 + ss];
                    mma_f16(cp, aH[mi], bH + 2 * ss);
                    mma_f16(cp, aL[mi], bH + 2 * ss);
                    mma_f16(cp, aH[mi], bL + 2 * ss);
                }
            }
        }
    }

#pragma unroll
    for (int ni = 0; ni < 8; ni++) {
        const int c0 = warp_n + ni * 8 + ((lane & 3) << 1);
        if (sMask[c0]) {
            acc[0][ni][0] = -10000.f; acc[0][ni][2] = -10000.f;
            acc[1][ni][0] = -10000.f; acc[1][ni][2] = -10000.f;
        }
        if (sMask[c0 + 1]) {
            acc[0][ni][1] = -10000.f; acc[0][ni][3] = -10000.f;
            acc[1][ni][1] = -10000.f; acc[1][ni][3] = -10000.f;
        }
    }

#pragma unroll
    for (int mi = 0; mi < 2; mi++)
#pragma unroll
        for (int rr = 0; rr < 2; rr++) {
            float mx = -1e30f;
#pragma unroll
            for (int ni = 0; ni < 8; ni++) {
                mx = fmaxf(mx, acc[mi][ni][rr * 2 + 0]);
                mx = fmaxf(mx, acc[mi][ni][rr * 2 + 1]);
            }
            mx = fmaxf(mx, __shfl_xor_sync(0xFFFFFFFFu, mx, 1));
            mx = fmaxf(mx, __shfl_xor_sync(0xFFFFFFFFu, mx, 2));
            const int row = warp_m + mi * 16 + rr * 8 + (lane >> 2);
            if ((lane & 3) == 0) sMax[half * 128 + row] = mx;
        }
    __syncthreads();

#pragma unroll
    for (int mi = 0; mi < 2; mi++)
#pragma unroll
        for (int rr = 0; rr < 2; rr++) {
            const int row = warp_m + mi * 16 + rr * 8 + (lane >> 2);
            const float m = fmaxf(sMax[row], sMax[128 + row]);
            float s = 0.f;
#pragma unroll
            for (int ni = 0; ni < 8; ni++) {
                float e0 = __expf(acc[mi][ni][rr * 2 + 0] - m);
                float e1 = __expf(acc[mi][ni][rr * 2 + 1] - m);
                acc[mi][ni][rr * 2 + 0] = e0;
                acc[mi][ni][rr * 2 + 1] = e1;
                s += e0 + e1;
            }
            s += __shfl_xor_sync(0xFFFFFFFFu, s, 1);
            s += __shfl_xor_sync(0xFFFFFFFFu, s, 2);
            if ((lane & 3) == 0) sSum[half * 128 + row] = s;
        }
    __syncthreads();

    {
        hf* Ph = (hf*)(dsm + AOFF_PH);
        hf* Pl = (hf*)(dsm + AOFF_PL);
#pragma unroll
        for (int mi = 0; mi < 2; mi++)
#pragma unroll
            for (int rr = 0; rr < 2; rr++) {
                const int row = warp_m + mi * 16 + rr * 8 + (lane >> 2);
                const float inv = 1.f / (sSum[row] + sSum[128 + row]);
#pragma unroll
                for (int ni = 0; ni < 8; ni++) {
                    const int col = warp_n + ni * 8 + ((lane & 3) << 1);
                    const float p0 = acc[mi][ni][rr * 2 + 0] * inv;
                    const float p1 = acc[mi][ni][rr * 2 + 1] * inv;
                    hf h0, l0, h1, l1;
                    split1(p0, h0, l0); split1(p1, h1, l1);
                    *(__half2*)&Ph[row * PS + col] = __halves2half2(h0, h1);
                    *(__half2*)&Pl[row * PS + col] = __halves2half2(l0, l1);
                }
            }
    }
    __syncthreads();

    if (write_probs) {
        const hf* Ph = (const hf*)(dsm + AOFF_PH);
        const hf* Pl = (const hf*)(dsm + AOFF_PL);
        float* pb = probs + (((size_t)h * CC + c) * RR) * RR;
#pragma unroll
        for (int p = 0; p < 16; p++) {
            const int row = p * 8 + (tid >> 5);
            const int col = (lane) * 4;
            const __half2* hp = (const __half2*)&Ph[row * PS + col];
            const __half2* lp = (const __half2*)&Pl[row * PS + col];
            float2 h0 = __half22float2(hp[0]);
            float2 h1 = __half22float2(hp[1]);
            float2 l0 = __half22float2(lp[0]);
            float2 l1 = __half22float2(lp[1]);
            float4 v = make_float4(h0.x + l0.x, h0.y + l0.y,
                                   h1.x + l1.x, h1.y + l1.y);
            *(float4*)&pb[(size_t)row * RR + col] = v;
        }
    }

    float acc2[2][4][4];
#pragma unroll
    for (int mi = 0; mi < 2; mi++)
#pragma unroll
        for (int ni = 0; ni < 4; ni++)
#pragma unroll
            for (int q = 0; q < 4; q++) acc2[mi][ni][q] = 0.f;

    {
        const int warp_nd = half << 5;
#pragma unroll
        for (int ks = 0; ks < 8; ks++) {
            const int kk = ks << 4;
            uint32_t aH[2][4], aL[2][4];
#pragma unroll
            for (int mi = 0; mi < 2; mi++) {
                const uint32_t off =
                    (uint32_t)((warp_m + mi * 16 + a_r) * PS + kk + a_k) * 2;
                ldsm4(aH[mi], u0 + AOFF_PH + off);
                ldsm4(aL[mi], u0 + AOFF_PL + off);
            }
#pragma unroll
            for (int np = 0; np < 2; np++) {
                uint32_t bH[4], bL[4];
                const uint32_t off =
                    (uint32_t)((kk + v_r) * QS + warp_nd + np * 16 + v_c) * 2;
                ldsm4t(bH, u0 + AOFF_VH + off);
                ldsm4t(bL, u0 + AOFF_VL + off);
#pragma unroll
                for (int mi = 0; mi < 2; mi++) {
#pragma unroll
                    for (int ss = 0; ss < 2; ss++) {
                        float* cp = acc2[mi][np * 2 + ss];
                        mma_f16(cp, aH[mi], bH + 2 * ss);
                        mma_f16(cp, aH[mi], bL + 2 * ss);
                        mma_f16(cp, aL[mi], bH + 2 * ss);
                    }
                }
            }
        }
    }
    __syncthreads();

    {
        hf* Chs = (hf*)(dsm + AOFF_CH);
        hf* Cls = (hf*)(dsm + AOFF_CL);
        const int warp_nd = half << 5;
#pragma unroll
        for (int mi = 0; mi < 2; mi++)
#pragma unroll
            for (int rr = 0; rr < 2; rr++) {
                const int i = warp_m + mi * 16 + rr * 8 + (lane >> 2);
#pragma unroll
                for (int ni = 0; ni < 4; ni++) {
                    const int d = warp_nd + ni * 8 + ((lane & 3) << 1);
                    hf h0, l0, h1, l1;
                    split1(acc2[mi][ni][rr * 2 + 0], h0, l0);
                    split1(acc2[mi][ni][rr * 2 + 1], h1, l1);
                    *(__half2*)&Chs[i * QS + d] = __halves2half2(h0, h1);
                    *(__half2*)&Cls[i * QS + d] = __halves2half2(l0, l1);
                }
            }
    }
    __syncthreads();
    {
        const hf* Chs = (const hf*)(dsm + AOFF_CH);
        const hf* Cls = (const hf*)(dsm + AOFF_CL);
#pragma unroll
        for (int p = 0; p < 8; p++) {
            const int lr = p * 32 + (tid >> 3);
            const int arr = lr >> 7;
            const int i = lr & 127;
            const hf* src = arr ? Cls : Chs;
            uint4 v = *(const uint4*)&src[i * QS + (tid & 7) * 8];
            hf* dst = arr ? g_Cl : g_Ch;
            *(uint4*)&dst[((size_t)i * CC + c) * EMB + h * DKD + (tid & 7) * 8] = v;
        }
    }
}

// ---------------------------------------------------------------------------
extern "C" void kernel_launch(void* const* d_in, const int* in_sizes, int n_in,
                              void* d_out, int out_size)
{
    const float*         x    = (const float*)d_in[0];
    const unsigned char* mask = (const unsigned char*)d_in[1];
    const float* Wq = (const float*)d_in[2];
    const float* bq = (const float*)d_in[3];
    const float* Wk = (const float*)d_in[4];
    const float* bk = (const float*)d_in[5];
    const float* Wv = (const float*)d_in[6];
    const float* bv = (const float*)d_in[7];
    const float* Wo = (const float*)d_in[8];
    const float* bo = (const float*)d_in[9];
    float* out = (float*)d_out;

    const long long OUT_E   = (long long)NT * EMB;
    const long long PROBS_E = (long long)NH * CC * RR * RR;

    float* probs = nullptr;
    int write_probs = 0;
    int do_output = 1;
    if ((long long)out_size >= OUT_E + PROBS_E) {
        probs = out + OUT_E;
        write_probs = 1;
    } else if ((long long)out_size == PROBS_E) {
        probs = out;
        write_probs = 1;
        do_output = 0;
    }

    void *xh, *xl, *wh, *qh_, *ql_, *kh_, *kl_, *vh_, *vl_, *ch, *cl;
    cudaGetSymbolAddress(&xh, g_Xh);  cudaGetSymbolAddress(&xl, g_Xl);
    cudaGetSymbolAddress(&wh, g_Wh);
    cudaGetSymbolAddress(&qh_, g_Qh); cudaGetSymbolAddress(&ql_, g_Ql);
    cudaGetSymbolAddress(&kh_, g_Kh); cudaGetSymbolAddress(&kl_, g_Kl);
    cudaGetSymbolAddress(&vh_, g_Vh); cudaGetSymbolAddress(&vl_, g_Vl);
    cudaGetSymbolAddress(&ch, g_Ch);  cudaGetSymbolAddress(&cl, g_Cl);

    hf* Xh = (hf*)xh; hf* Xl = (hf*)xl;
    hf* Wh = (hf*)wh;
    const size_t WSZ = (size_t)EMB * EMB;

    static int attr_set = 0;
    if (!attr_set) {
        cudaFuncSetAttribute(gemm_qkv,
                             cudaFuncAttributeMaxDynamicSharedMemorySize, GEMM_SMEM);
        cudaFuncSetAttribute(gemm_o,
                             cudaFuncAttributeMaxDynamicSharedMemorySize, GEMM_SMEM);
        cudaFuncSetAttribute(attn_mma,
                             cudaFuncAttributeMaxDynamicSharedMemorySize, ATTN_SMEM);
        attr_set = 1;
    }

    split_kernel<<<(NT * EMB / 4 + 255) / 256, 256>>>(x, Xh, Xl, NT * EMB / 4);
    split_w4_kernel<<<dim3((unsigned)((WSZ / 4 + 255) / 256), 4), 256>>>(
        Wq, Wk, Wv, Wo, Wh, (int)(WSZ / 4));

    gemm_qkv<<<dim3(6, 256, 3), 256, GEMM_SMEM>>>(
        Xh, Xl, Wh, bq, bk, bv,
        (hf*)qh_, (hf*)ql_, (hf*)kh_, (hf*)kl_, (hf*)vh_, (hf*)vl_);

    attn_mma<<<dim3(CC, NH), 256, ATTN_SMEM>>>(
        (const hf*)qh_, (const hf*)ql_, (const hf*)kh_, (const hf*)kl_,
        (const hf*)vh_, (const hf*)vl_, mask, probs, write_probs);

    if (do_output)
        gemm_o<<<dim3(6, 256), 256, GEMM_SMEM>>>(
            (const hf*)ch, (const hf*)cl, Wh + 3 * WSZ, bo, out);
}

// round 16
// speedup vs baseline: 1.4309x; 1.0064x over previous
#include <cuda_runtime.h>
#include <cuda_fp16.h>
#include <cstdint>

#define RR   128
#define CC   256
#define EMB  768
#define NH   12
#define DKD  64
#define NT   (RR * CC)          // 32768 tokens

typedef __half hf;

// ---------------- scratch (__device__ globals, allocation-free) -------------
__device__ hf g_Xh[(size_t)NT * EMB];
__device__ hf g_Xl[(size_t)NT * EMB];
__device__ hf g_Wh[4][(size_t)EMB * EMB];           // W hi only (2-term GEMM)
__device__ hf g_Qh[(size_t)CC * NH * RR * DKD];     // [c][h][i][d]
__device__ hf g_Ql[(size_t)CC * NH * RR * DKD];
__device__ hf g_Kh[(size_t)CC * NH * RR * DKD];
__device__ hf g_Kl[(size_t)CC * NH * RR * DKD];
__device__ hf g_Vh[(size_t)CC * NH * RR * DKD];     // [c][h][i][d]
__device__ hf g_Vl[(size_t)CC * NH * RR * DKD];
__device__ hf g_Ch[(size_t)NT * EMB];               // ctx hi/lo [t][e]
__device__ hf g_Cl[(size_t)NT * EMB];

// ---------------------------- helpers --------------------------------------
__device__ __forceinline__ uint32_t smem_u32(const void* p) {
    uint32_t a;
    asm("{ .reg .u64 t; cvta.to.shared.u64 t, %1; cvt.u32.u64 %0, t; }"
        : "=r"(a) : "l"(p));
    return a;
}
__device__ __forceinline__ void ldsm4(uint32_t* r, uint32_t addr) {
    asm volatile("ldmatrix.sync.aligned.m8n8.x4.shared.b16 {%0,%1,%2,%3}, [%4];"
                 : "=r"(r[0]), "=r"(r[1]), "=r"(r[2]), "=r"(r[3]) : "r"(addr));
}
__device__ __forceinline__ void ldsm4t(uint32_t* r, uint32_t addr) {
    asm volatile("ldmatrix.sync.aligned.m8n8.x4.trans.shared.b16 {%0,%1,%2,%3}, [%4];"
                 : "=r"(r[0]), "=r"(r[1]), "=r"(r[2]), "=r"(r[3]) : "r"(addr));
}
__device__ __forceinline__ void mma_f16(float* c, const uint32_t* a,
                                        const uint32_t* b) {
    asm volatile(
        "mma.sync.aligned.m16n8k16.row.col.f32.f16.f16.f32 "
        "{%0,%1,%2,%3}, {%4,%5,%6,%7}, {%8,%9}, {%0,%1,%2,%3};"
        : "+f"(c[0]), "+f"(c[1]), "+f"(c[2]), "+f"(c[3])
        : "r"(a[0]), "r"(a[1]), "r"(a[2]), "r"(a[3]), "r"(b[0]), "r"(b[1]));
}
#define CP_ASYNC(dst, src) \
    asm volatile("cp.async.cg.shared.global [%0], [%1], 16;" \
                 :: "r"(dst), "l"(src) : "memory")
#define CP_COMMIT() asm volatile("cp.async.commit_group;" ::: "memory")
#define CP_WAIT(n)  asm volatile("cp.async.wait_group %0;" :: "n"(n) : "memory")

__device__ __forceinline__ void split1(float v, hf& h, hf& l) {
    h = __float2half_rn(v);
    l = __float2half_rn(v - __half2float(h));
}

// ---------------------------------------------------------------------------
// fp32 -> (hi, lo) fp16 splits
// ---------------------------------------------------------------------------
__global__ __launch_bounds__(256) void split_kernel(
    const float* __restrict__ src, hf* __restrict__ hi,
    hf* __restrict__ lo, int n4)
{
    int i = blockIdx.x * blockDim.x + threadIdx.x;
    if (i >= n4) return;
    float4 v = ((const float4*)src)[i];
    float a[4] = {v.x, v.y, v.z, v.w};
    hf h[4], l[4];
#pragma unroll
    for (int j = 0; j < 4; j++) split1(a[j], h[j], l[j]);
    ((__half2*)hi)[2 * i + 0] = __halves2half2(h[0], h[1]);
    ((__half2*)hi)[2 * i + 1] = __halves2half2(h[2], h[3]);
    ((__half2*)lo)[2 * i + 0] = __halves2half2(l[0], l[1]);
    ((__half2*)lo)[2 * i + 1] = __halves2half2(l[2], l[3]);
}

// all 4 weight matrices, hi only (W-lo term dropped in 2-term GEMM)
__global__ __launch_bounds__(256) void split_w4_kernel(
    const float* __restrict__ w0, const float* __restrict__ w1,
    const float* __restrict__ w2, const float* __restrict__ w3,
    hf* __restrict__ hiBase, int n4)
{
    const int j = blockIdx.y;
    const float* src = (j == 0) ? w0 : (j == 1) ? w1 : (j == 2) ? w2 : w3;
    hf* hi = hiBase + (size_t)j * EMB * EMB;
    int i = blockIdx.x * blockDim.x + threadIdx.x;
    if (i >= n4) return;
    float4 v = ((const float4*)src)[i];
    ((__half2*)hi)[2 * i + 0] =
        __halves2half2(__float2half_rn(v.x), __float2half_rn(v.y));
    ((__half2*)hi)[2 * i + 1] =
        __halves2half2(__float2half_rn(v.z), __float2half_rn(v.w));
}

// ---------------------------------------------------------------------------
// GEMM mainloop: 128x128 CTA tile, BK=32, 3-stage cp.async pipeline (one
// __syncthreads per iter), 2-term fp16 mma: D = Ah*Bh + Al*Bh.
// Accumulator-major MMA order (R12 regression evidence — do not reorder).
// ---------------------------------------------------------------------------
#define BK        32
#define SSTR      40
#define TILE_B    (128 * SSTR * 2)          // 10240 B
#define STAGE_B   (3 * TILE_B)              // 30720 B (Ah, Al, Bh)
#define ESTR      136                        // f16 epilogue smem stride
#define ESTR4     132                        // fp32 epilogue smem stride
#define GEMM_SMEM (3 * STAGE_B)             // 92160 B (>= epilogue 69632)
#define NSTEP     (EMB / BK)                // 24

__device__ __forceinline__ void gemm_mainloop(
    const hf* __restrict__ Ah, const hf* __restrict__ Al,
    const hf* __restrict__ Bh,
    int m0, int n0, uint32_t u0, int tid, float (&acc)[2][8][4])
{
    const int lane   = tid & 31;
    const int wid    = tid >> 5;
    const int warp_m = (wid & 3) << 5;
    const int warp_n = (wid >> 2) << 6;

    const int a_r = lane & 15;
    const int a_k = (lane >> 4) << 3;
    const int b_n = (lane & 7) + ((lane >> 4) << 3);
    const int b_k = ((lane >> 3) & 1) << 3;

    const int f_row = tid >> 2;
    const int f_c16 = tid & 3;

#define FILL(stage, k0) do {                                                   \
        const uint32_t sb = u0 + (stage) * STAGE_B;                            \
        _Pragma("unroll")                                                      \
        for (int t = 0; t < 3; t++) {                                          \
            const hf* sp = (t == 0) ? Ah : (t == 1) ? Al : Bh;                 \
            const int rb = (t < 2) ? m0 : n0;                                  \
            _Pragma("unroll")                                                  \
            for (int sub = 0; sub < 2; sub++) {                                \
                const int row = f_row + sub * 64;                              \
                CP_ASYNC(sb + t * TILE_B + row * (SSTR * 2) + f_c16 * 16,      \
                         sp + (size_t)(rb + row) * EMB + (k0) + f_c16 * 8);    \
            }                                                                  \
        }                                                                      \
        CP_COMMIT();                                                           \
    } while (0)

    FILL(0, 0);
    FILL(1, BK);

    for (int s = 0; s < NSTEP; s++) {
        if (s + 1 < NSTEP) { CP_WAIT(1); }   // fill(s) done; fill(s+1) may fly
        else               { CP_WAIT(0); }
        __syncthreads();                     // fills visible + compute(s-1) done
        if (s + 2 < NSTEP) FILL((s + 2) % 3, (s + 2) * BK);

        const uint32_t sb  = u0 + (s % 3) * STAGE_B;
        const uint32_t uAh = sb;
        const uint32_t uAl = sb + TILE_B;
        const uint32_t uBh = sb + 2 * TILE_B;

#pragma unroll
        for (int ks = 0; ks < 2; ks++) {
            const int kk = ks << 4;
            uint32_t aH[2][4], aL[2][4];
#pragma unroll
            for (int mi = 0; mi < 2; mi++) {
                const uint32_t off =
                    (uint32_t)((warp_m + mi * 16 + a_r) * SSTR + kk + a_k) * 2;
                ldsm4(aH[mi], uAh + off);
                ldsm4(aL[mi], uAl + off);
            }
#pragma unroll
            for (int np = 0; np < 4; np++) {
                uint32_t bH[4];
                const uint32_t off =
                    (uint32_t)((warp_n + np * 16 + b_n) * SSTR + kk + b_k) * 2;
                ldsm4(bH, uBh + off);
#pragma unroll
                for (int mi = 0; mi < 2; mi++) {
#pragma unroll
                    for (int ss = 0; ss < 2; ss++) {
                        float* c = acc[mi][np * 2 + ss];
                        mma_f16(c, aH[mi], bH + 2 * ss);
                        mma_f16(c, aL[mi], bH + 2 * ss);
                    }
                }
            }
        }
    }
#undef FILL
}

// Fused QKV projection: blockIdx.z selects {Q, K, V}; outputs [c][h][i][d]
__global__ __launch_bounds__(256, 2) void gemm_qkv(
    const hf* __restrict__ Xh, const hf* __restrict__ Xl,
    const hf* __restrict__ WhB,
    const float* __restrict__ bq, const float* __restrict__ bk,
    const float* __restrict__ bv,
    hf* __restrict__ qh, hf* __restrict__ ql,
    hf* __restrict__ kh, hf* __restrict__ kl,
    hf* __restrict__ vh, hf* __restrict__ vl)
{
    extern __shared__ char dsm[];
    const uint32_t u0 = smem_u32(dsm);
    const int tid  = threadIdx.x;
    const int lane = tid & 31;
    const int wid  = tid >> 5;
    const int m0 = blockIdx.y << 7;
    const int n0 = blockIdx.x << 7;
    const int z  = blockIdx.z;

    const size_t WSZ = (size_t)EMB * EMB;
    const hf* Bh = WhB + (size_t)z * WSZ;
    const float* bias = (z == 0) ? bq : (z == 1) ? bk : bv;
    const float scale = (z == 0) ? 0.125f : 1.0f;
    hf* oh = (z == 0) ? qh : (z == 1) ? kh : vh;
    hf* ol = (z == 0) ? ql : (z == 1) ? kl : vl;

    float acc[2][8][4];
#pragma unroll
    for (int mi = 0; mi < 2; mi++)
#pragma unroll
        for (int ni = 0; ni < 8; ni++)
#pragma unroll
            for (int q = 0; q < 4; q++) acc[mi][ni][q] = 0.f;

    gemm_mainloop(Xh, Xl, Bh, m0, n0, u0, tid, acc);
    __syncthreads();   // mainloop smem free for epilogue staging

    // ---- stage to smem (bias + scale + split), then coalesced store ----
    hf* Eh = (hf*)dsm;
    hf* El = (hf*)(dsm + 128 * ESTR * 2);
    const int warp_m = (wid & 3) << 5;
    const int warp_n = (wid >> 2) << 6;
#pragma unroll
    for (int mi = 0; mi < 2; mi++)
#pragma unroll
        for (int rr = 0; rr < 2; rr++) {
            const int row = warp_m + mi * 16 + rr * 8 + (lane >> 2);
#pragma unroll
            for (int ni = 0; ni < 8; ni++) {
                const int col = warp_n + ni * 8 + ((lane & 3) << 1);
                const float2 bv2 = *(const float2*)&bias[n0 + col];
                const float v0 = (acc[mi][ni][rr * 2 + 0] + bv2.x) * scale;
                const float v1 = (acc[mi][ni][rr * 2 + 1] + bv2.y) * scale;
                hf h0, l0, h1, l1;
                split1(v0, h0, l0); split1(v1, h1, l1);
                *(__half2*)&Eh[row * ESTR + col] = __halves2half2(h0, h1);
                *(__half2*)&El[row * ESTR + col] = __halves2half2(l0, l1);
            }
        }
    __syncthreads();

    const int irow  = m0 >> 8;
    const int ccol0 = m0 & 255;
    const int hh0   = n0 >> 6;
#pragma unroll
    for (int p = 0; p < 16; p++) {
        const int lr = p * 32 + (tid >> 3);   // 0..511
        const int arr = lr >> 8;              // 0 hi, 1 lo
        const int r = lr & 255;
        const int ml = r >> 1;
        const int hl = r & 1;
        const hf* src = arr ? El : Eh;
        uint4 v = *(const uint4*)&src[ml * ESTR + hl * 64 + (tid & 7) * 8];
        hf* dst = arr ? ol : oh;
        *(uint4*)&dst[(((size_t)(ccol0 + ml) * NH + hh0 + hl) * RR + irow) * DKD
                      + (tid & 7) * 8] = v;
    }
}

// Output projection: fp32 out, staged epilogue
__global__ __launch_bounds__(256, 2) void gemm_o(
    const hf* __restrict__ Ch, const hf* __restrict__ Cl,
    const hf* __restrict__ Wh,
    const float* __restrict__ bias, float* __restrict__ out)
{
    extern __shared__ char dsm[];
    const uint32_t u0 = smem_u32(dsm);
    const int tid  = threadIdx.x;
    const int lane = tid & 31;
    const int wid  = tid >> 5;
    const int m0 = blockIdx.y << 7;
    const int n0 = blockIdx.x << 7;

    float acc[2][8][4];
#pragma unroll
    for (int mi = 0; mi < 2; mi++)
#pragma unroll
        for (int ni = 0; ni < 8; ni++)
#pragma unroll
            for (int q = 0; q < 4; q++) acc[mi][ni][q] = 0.f;

    gemm_mainloop(Ch, Cl, Wh, m0, n0, u0, tid, acc);
    __syncthreads();

    float* Ef = (float*)dsm;
    const int warp_m = (wid & 3) << 5;
    const int warp_n = (wid >> 2) << 6;
#pragma unroll
    for (int mi = 0; mi < 2; mi++)
#pragma unroll
        for (int rr = 0; rr < 2; rr++) {
            const int row = warp_m + mi * 16 + rr * 8 + (lane >> 2);
#pragma unroll
            for (int ni = 0; ni < 8; ni++) {
                const int col = warp_n + ni * 8 + ((lane & 3) << 1);
                const float2 bv2 = *(const float2*)&bias[n0 + col];
                *(float2*)&Ef[row * ESTR4 + col] =
                    make_float2(acc[mi][ni][rr * 2 + 0] + bv2.x,
                                acc[mi][ni][rr * 2 + 1] + bv2.y);
            }
        }
    __syncthreads();
#pragma unroll
    for (int p = 0; p < 16; p++) {
        const int ml = p * 8 + (tid >> 5);
        float4 v = *(const float4*)&Ef[ml * ESTR4 + (tid & 31) * 4];
        *(float4*)&out[(size_t)(m0 + ml) * EMB + n0 + (tid & 31) * 4] = v;
    }
}

// ---------------------------------------------------------------------------
// Tensor-core attention (R15 structure; split cp.async waits: S starts while
// V tiles are still in flight; 3-term kept — attn is latency-bound, not MMA)
// ---------------------------------------------------------------------------
#define QS 72
#define PS 136

#define AOFF_QH  0
#define AOFF_QL  (AOFF_QH + 128 * QS * 2)
#define AOFF_KH  (AOFF_QL + 128 * QS * 2)
#define AOFF_KL  (AOFF_KH + 128 * QS * 2)
#define AOFF_VH  (AOFF_KL + 128 * QS * 2)
#define AOFF_VL  (AOFF_VH + 128 * QS * 2)
#define AOFF_ST  (AOFF_VL + 128 * QS * 2)
#define AOFF_MK  (AOFF_ST + 2048)
#define ATTN_SMEM (AOFF_MK + 128)
#define AOFF_PH  0
#define AOFF_PL  (AOFF_PH + 128 * PS * 2)
#define AOFF_CH  0
#define AOFF_CL  (AOFF_CH + 128 * QS * 2)

__global__ __launch_bounds__(256, 2) void attn_mma(
    const hf* __restrict__ qh, const hf* __restrict__ ql,
    const hf* __restrict__ kh, const hf* __restrict__ kl,
    const hf* __restrict__ vh, const hf* __restrict__ vl,
    const unsigned char* __restrict__ mask,
    float* __restrict__ probs, int write_probs)
{
    extern __shared__ char dsm[];
    const uint32_t u0 = smem_u32(dsm);
    float* sMax = (float*)(dsm + AOFF_ST);
    float* sSum = sMax + 256;
    unsigned char* sMask = (unsigned char*)(dsm + AOFF_MK);

    const int c   = blockIdx.x;
    const int h   = blockIdx.y;
    const int tid = threadIdx.x;
    const int lane = tid & 31;
    const int wid  = tid >> 5;
    const size_t base = (((size_t)c * NH + h) * RR) * DKD;

    // ---- loads: group 1 = Q/K (needed for S), group 2 = V (needed later) ----
    {
        const int row_q = tid >> 1;
        const int c16_q = tid & 1;
        const hf* srcs[4] = {qh, ql, kh, kl};
        const uint32_t dsts[4] = {u0 + AOFF_QH, u0 + AOFF_QL,
                                  u0 + AOFF_KH, u0 + AOFF_KL};
#pragma unroll
        for (int t = 0; t < 4; t++) {
#pragma unroll
            for (int sub = 0; sub < 4; sub++) {
                const int cid = sub * 2 + c16_q;
                CP_ASYNC(dsts[t] + row_q * (QS * 2) + cid * 16,
                         srcs[t] + base + (size_t)row_q * DKD + cid * 8);
            }
        }
        CP_COMMIT();                     // group: Q/K
        const hf* srcs2[2] = {vh, vl};
        const uint32_t dsts2[2] = {u0 + AOFF_VH, u0 + AOFF_VL};
#pragma unroll
        for (int t = 0; t < 2; t++) {
#pragma unroll
            for (int sub = 0; sub < 4; sub++) {
                const int cid = sub * 2 + c16_q;
                CP_ASYNC(dsts2[t] + row_q * (QS * 2) + cid * 16,
                         srcs2[t] + base + (size_t)row_q * DKD + cid * 8);
            }
        }
        CP_COMMIT();                     // group: V
        if (tid < 128) sMask[tid] = mask[(size_t)tid * CC + c];
        CP_WAIT(1);                      // Q/K ready; V still in flight
    }
    __syncthreads();

    const int a_r = lane & 15;
    const int a_k = (lane >> 4) << 3;
    const int b_n = (lane & 7) + ((lane >> 4) << 3);
    const int b_k = ((lane >> 3) & 1) << 3;
    const int v_r = (((lane >> 3) & 1) << 3) + (lane & 7);
    const int v_c = (lane >> 4) << 3;
    const int warp_m = (wid & 3) << 5;
    const int half   = wid >> 2;
    const int warp_n = half << 6;

    float acc[2][8][4];
#pragma unroll
    for (int mi = 0; mi < 2; mi++)
#pragma unroll
        for (int ni = 0; ni < 8; ni++)
#pragma unroll
            for (int q = 0; q < 4; q++) acc[mi][ni][q] = 0.f;

#pragma unroll
    for (int ks = 0; ks < 4; ks++) {
        const int kk = ks << 4;
        uint32_t aH[2][4], aL[2][4];
#pragma unroll
        for (int mi = 0; mi < 2; mi++) {
            const uint32_t off =
                (uint32_t)((warp_m + mi * 16 + a_r) * QS + kk + a_k) * 2;
            ldsm4(aH[mi], u0 + AOFF_QH + off);
            ldsm4(aL[mi], u0 + AOFF_QL + off);
        }
#pragma unroll
        for (int np = 0; np < 4; np++) {
            uint32_t bH[4], bL[4];
            const uint32_t off =
                (uint32_t)((warp_n + np * 16 + b_n) * QS + kk + b_k) * 2;
            ldsm4(bH, u0 + AOFF_KH + off);
            ldsm4(bL, u0 + AOFF_KL + off);
#pragma unroll
            for (int mi = 0; mi < 2; mi++) {
#pragma unroll
                for (int ss = 0; ss < 2; ss++) {
                    float* cp = acc[mi][np * 2 + ss];
                    mma_f16(cp, aH[mi], bH + 2 * ss);
                    mma_f16(cp, aL[mi], bH + 2 * ss);
                    mma_f16(cp, aH[mi], bL + 2 * ss);
                }
            }
        }
    }

#pragma unroll
    for (int ni = 0; ni < 8; ni++) {
        const int c0 = warp_n + ni * 8 + ((lane & 3) << 1);
        if (sMask[c0]) {
            acc[0][ni][0] = -10000.f; acc[0][ni][2] = -10000.f;
            acc[1][ni][0] = -10000.f; acc[1][ni][2] = -10000.f;
        }
        if (sMask[c0 + 1]) {
            acc[0][ni][1] = -10000.f; acc[0][ni][3] = -10000.f;
            acc[1][ni][1] = -10000.f; acc[1][ni][3] = -10000.f;
        }
    }

#pragma unroll
    for (int mi = 0; mi < 2; mi++)
#pragma unroll
        for (int rr = 0; rr < 2; rr++) {
            float mx = -1e30f;
#pragma unroll
            for (int ni = 0; ni < 8; ni++) {
                mx = fmaxf(mx, acc[mi][ni][rr * 2 + 0]);
                mx = fmaxf(mx, acc[mi][ni][rr * 2 + 1]);
            }
            mx = fmaxf(mx, __shfl_xor_sync(0xFFFFFFFFu, mx, 1));
            mx = fmaxf(mx, __shfl_xor_sync(0xFFFFFFFFu, mx, 2));
            const int row = warp_m + mi * 16 + rr * 8 + (lane >> 2);
            if ((lane & 3) == 0) sMax[half * 128 + row] = mx;
        }
    __syncthreads();

#pragma unroll
    for (int mi = 0; mi < 2; mi++)
#pragma unroll
        for (int rr = 0; rr < 2; rr++) {
            const int row = warp_m + mi * 16 + rr * 8 + (lane >> 2);
            const float m = fmaxf(sMax[row], sMax[128 + row]);
            float s = 0.f;
#pragma unroll
            for (int ni = 0; ni < 8; ni++) {
                float e0 = __expf(acc[mi][ni][rr * 2 + 0] - m);
                float e1 = __expf(acc[mi][ni][rr * 2 + 1] - m);
                acc[mi][ni][rr * 2 + 0] = e0;
                acc[mi][ni][rr * 2 + 1] = e1;
                s += e0 + e1;
            }
            s += __shfl_xor_sync(0xFFFFFFFFu, s, 1);
            s += __shfl_xor_sync(0xFFFFFFFFu, s, 2);
            if ((lane & 3) == 0) sSum[half * 128 + row] = s;
        }
    __syncthreads();

    {
        hf* Ph = (hf*)(dsm + AOFF_PH);
        hf* Pl = (hf*)(dsm + AOFF_PL);
#pragma unroll
        for (int mi = 0; mi < 2; mi++)
#pragma unroll
            for (int rr = 0; rr < 2; rr++) {
                const int row = warp_m + mi * 16 + rr * 8 + (lane >> 2);
                const float inv = 1.f / (sSum[row] + sSum[128 + row]);
#pragma unroll
                for (int ni = 0; ni < 8; ni++) {
                    const int col = warp_n + ni * 8 + ((lane & 3) << 1);
                    const float p0 = acc[mi][ni][rr * 2 + 0] * inv;
                    const float p1 = acc[mi][ni][rr * 2 + 1] * inv;
                    hf h0, l0, h1, l1;
                    split1(p0, h0, l0); split1(p1, h1, l1);
                    *(__half2*)&Ph[row * PS + col] = __halves2half2(h0, h1);
                    *(__half2*)&Pl[row * PS + col] = __halves2half2(l0, l1);
                }
            }
    }
    CP_WAIT(0);        // V tiles landed (overlapped with all of S + softmax)
    __syncthreads();

    if (write_probs) {
        const hf* Ph = (const hf*)(dsm + AOFF_PH);
        const hf* Pl = (const hf*)(dsm + AOFF_PL);
        float* pb = probs + (((size_t)h * CC + c) * RR) * RR;
#pragma unroll
        for (int p = 0; p < 16; p++) {
            const int row = p * 8 + (tid >> 5);
            const int col = (lane) * 4;
            const __half2* hp = (const __half2*)&Ph[row * PS + col];
            const __half2* lp = (const __half2*)&Pl[row * PS + col];
            float2 h0 = __half22float2(hp[0]);
            float2 h1 = __half22float2(hp[1]);
            float2 l0 = __half22float2(lp[0]);
            float2 l1 = __half22float2(lp[1]);
            float4 v = make_float4(h0.x + l0.x, h0.y + l0.y,
                                   h1.x + l1.x, h1.y + l1.y);
            *(float4*)&pb[(size_t)row * RR + col] = v;
        }
    }

    float acc2[2][4][4];
#pragma unroll
    for (int mi = 0; mi < 2; mi++)
#pragma unroll
        for (int ni = 0; ni < 4; ni++)
#pragma unroll
            for (int q = 0; q < 4; q++) acc2[mi][ni][q] = 0.f;

    {
        const int warp_nd = half << 5;
#pragma unroll
        for (int ks = 0; ks < 8; ks++) {
            const int kk = ks << 4;
            uint32_t aH[2][4], aL[2][4];
#pragma unroll
            for (int mi = 0; mi < 2; mi++) {
                const uint32_t off =
                    (uint32_t)((warp_m + mi * 16 + a_r) * PS + kk + a_k) * 2;
                ldsm4(aH[mi], u0 + AOFF_PH + off);
                ldsm4(aL[mi], u0 + AOFF_PL + off);
            }
#pragma unroll
            for (int np = 0; np < 2; np++) {
                uint32_t bH[4], bL[4];
                const uint32_t off =
                    (uint32_t)((kk + v_r) * QS + warp_nd + np * 16 + v_c) * 2;
                ldsm4t(bH, u0 + AOFF_VH + off);
                ldsm4t(bL, u0 + AOFF_VL + off);
#pragma unroll
                for (int mi = 0; mi < 2; mi++) {
#pragma unroll
                    for (int ss = 0; ss < 2; ss++) {
                        float* cp = acc2[mi][np * 2 + ss];
                        mma_f16(cp, aH[mi], bH + 2 * ss);
                        mma_f16(cp, aH[mi], bL + 2 * ss);
                        mma_f16(cp, aL[mi], bH + 2 * ss);
                    }
                }
            }
        }
    }
    __syncthreads();

    {
        hf* Chs = (hf*)(dsm + AOFF_CH);
        hf* Cls = (hf*)(dsm + AOFF_CL);
        const int warp_nd = half << 5;
#pragma unroll
        for (int mi = 0; mi < 2; mi++)
#pragma unroll
            for (int rr = 0; rr < 2; rr++) {
                const int i = warp_m + mi * 16 + rr * 8 + (lane >> 2);
#pragma unroll
                for (int ni = 0; ni < 4; ni++) {
                    const int d = warp_nd + ni * 8 + ((lane & 3) << 1);
                    hf h0, l0, h1, l1;
                    split1(acc2[mi][ni][rr * 2 + 0], h0, l0);
                    split1(acc2[mi][ni][rr * 2 + 1], h1, l1);
                    *(__half2*)&Chs[i * QS + d] = __halves2half2(h0, h1);
                    *(__half2*)&Cls[i * QS + d] = __halves2half2(l0, l1);
                }
            }
    }
    __syncthreads();
    {
        const hf* Chs = (const hf*)(dsm + AOFF_CH);
        const hf* Cls = (const hf*)(dsm + AOFF_CL);
#pragma unroll
        for (int p = 0; p < 8; p++) {
            const int lr = p * 32 + (tid >> 3);
            const int arr = lr >> 7;
            const int i = lr & 127;
            const hf* src = arr ? Cls : Chs;
            uint4 v = *(const uint4*)&src[i * QS + (tid & 7) * 8];
            hf* dst = arr ? g_Cl : g_Ch;
            *(uint4*)&dst[((size_t)i * CC + c) * EMB + h * DKD + (tid & 7) * 8] = v;
        }
    }
}

// ---------------------------------------------------------------------------
extern "C" void kernel_launch(void* const* d_in, const int* in_sizes, int n_in,
                              void* d_out, int out_size)
{
    const float*         x    = (const float*)d_in[0];
    const unsigned char* mask = (const unsigned char*)d_in[1];
    const float* Wq = (const float*)d_in[2];
    const float* bq = (const float*)d_in[3];
    const float* Wk = (const float*)d_in[4];
    const float* bk = (const float*)d_in[5];
    const float* Wv = (const float*)d_in[6];
    const float* bv = (const float*)d_in[7];
    const float* Wo = (const float*)d_in[8];
    const float* bo = (const float*)d_in[9];
    float* out = (float*)d_out;

    const long long OUT_E   = (long long)NT * EMB;
    const long long PROBS_E = (long long)NH * CC * RR * RR;

    float* probs = nullptr;
    int write_probs = 0;
    int do_output = 1;
    if ((long long)out_size >= OUT_E + PROBS_E) {
        probs = out + OUT_E;
        write_probs = 1;
    } else if ((long long)out_size == PROBS_E) {
        probs = out;
        write_probs = 1;
        do_output = 0;
    }

    void *xh, *xl, *wh, *qh_, *ql_, *kh_, *kl_, *vh_, *vl_, *ch, *cl;
    cudaGetSymbolAddress(&xh, g_Xh);  cudaGetSymbolAddress(&xl, g_Xl);
    cudaGetSymbolAddress(&wh, g_Wh);
    cudaGetSymbolAddress(&qh_, g_Qh); cudaGetSymbolAddress(&ql_, g_Ql);
    cudaGetSymbolAddress(&kh_, g_Kh); cudaGetSymbolAddress(&kl_, g_Kl);
    cudaGetSymbolAddress(&vh_, g_Vh); cudaGetSymbolAddress(&vl_, g_Vl);
    cudaGetSymbolAddress(&ch, g_Ch);  cudaGetSymbolAddress(&cl, g_Cl);

    hf* Xh = (hf*)xh; hf* Xl = (hf*)xl;
    hf* Wh = (hf*)wh;
    const size_t WSZ = (size_t)EMB * EMB;

    static int attr_set = 0;
    if (!attr_set) {
        cudaFuncSetAttribute(gemm_qkv,
                             cudaFuncAttributeMaxDynamicSharedMemorySize, GEMM_SMEM);
        cudaFuncSetAttribute(gemm_o,
                             cudaFuncAttributeMaxDynamicSharedMemorySize, GEMM_SMEM);
        cudaFuncSetAttribute(attn_mma,
                             cudaFuncAttributeMaxDynamicSharedMemorySize, ATTN_SMEM);
        attr_set = 1;
    }

    split_kernel<<<(NT * EMB / 4 + 255) / 256, 256>>>(x, Xh, Xl, NT * EMB / 4);
    split_w4_kernel<<<dim3((unsigned)((WSZ / 4 + 255) / 256), 4), 256>>>(
        Wq, Wk, Wv, Wo, Wh, (int)(WSZ / 4));

    gemm_qkv<<<dim3(6, 256, 3), 256, GEMM_SMEM>>>(
        Xh, Xl, Wh, bq, bk, bv,
        (hf*)qh_, (hf*)ql_, (hf*)kh_, (hf*)kl_, (hf*)vh_, (hf*)vl_);

    attn_mma<<<dim3(CC, NH), 256, ATTN_SMEM>>>(
        (const hf*)qh_, (const hf*)ql_, (const hf*)kh_, (const hf*)kl_,
        (const hf*)vh_, (const hf*)vl_, mask, probs, write_probs);

    if (do_output)
        gemm_o<<<dim3(6, 256), 256, GEMM_SMEM>>>(
            (const hf*)ch, (const hf*)cl, Wh + 3 * WSZ, bo, out);
}